// round 13
// baseline (speedup 1.0000x reference)
#include <cuda_runtime.h>
#include <cuda_fp16.h>
#include <cstdint>

#define NBX 512
#define NBY 512
#define ITEMS 8

// fp16-packed 2x2 neighborhood of utilization_map (2 MB):
// entry[bx*NBY+by] = { h2(u00,u01), h2(u10,u11) }
__device__ __align__(8) uint2 g_packu[NBX * NBY];

__global__ __launch_bounds__(256)
void pack_kernel(const float* __restrict__ umap)
{
    int t = blockIdx.x * blockDim.x + threadIdx.x;
    if (t >= NBX * NBY) return;
    int bx = t / NBY;
    int by = t % NBY;
    int by1 = min(by + 1, NBY - 1);
    int bx1 = min(bx + 1, NBX - 1);
    float u00 = __ldg(&umap[bx  * NBY + by ]);
    float u01 = __ldg(&umap[bx  * NBY + by1]);
    float u10 = __ldg(&umap[bx1 * NBY + by ]);
    float u11 = __ldg(&umap[bx1 * NBY + by1]);
    __half2 a = __floats2half2_rn(u00, u01);
    __half2 b = __floats2half2_rn(u10, u11);
    uint2 pk;
    pk.x = *reinterpret_cast<unsigned int*>(&a);
    pk.y = *reinterpret_cast<unsigned int*>(&b);
    g_packu[t] = pk;
}

// Zero-fill for the general (non-covering) scatter case.
__global__ __launch_bounds__(256)
void zero_kernel(float4* __restrict__ out4, int nout4,
                 float* __restrict__ out, int nout)
{
    int t = blockIdx.x * blockDim.x + threadIdx.x;
    if (t < nout4) {
        float4 z; z.x = 0.f; z.y = 0.f; z.z = 0.f; z.w = 0.f;
        out4[t] = z;
    }
    int tail = nout4 * 4 + t;
    if (tail < nout) out[tail] = 0.0f;
}

__device__ __forceinline__ float area_of(float xv, float yv, float wv, float hv,
                                         uint2 u)
{
    float xh = xv + wv;
    float yh = yv + hv;
    int bx0 = min(max((int)floorf(xv), 0), NBX - 1);
    int by0 = min(max((int)floorf(yv), 0), NBY - 1);
    float fbx0 = (float)bx0;
    float fby0 = (float)by0;

    float ox0 = fmaxf(fminf(xh, fbx0 + 1.0f) - fmaxf(xv, fbx0), 0.0f);
    float ox1 = fmaxf(fminf(xh, fbx0 + 2.0f) - fmaxf(xv, fbx0 + 1.0f), 0.0f);
    if (bx0 + 1 >= NBX) ox1 = 0.0f;

    float oy0 = fmaxf(fminf(yh, fby0 + 1.0f) - fmaxf(yv, fby0), 0.0f);
    float oy1 = fmaxf(fminf(yh, fby0 + 2.0f) - fmaxf(yv, fby0 + 1.0f), 0.0f);
    if (by0 + 1 >= NBY) oy1 = 0.0f;

    __half2 ha = *reinterpret_cast<__half2*>(&u.x);
    __half2 hb = *reinterpret_cast<__half2*>(&u.y);
    float2 f0 = __half22float2(ha);   // (u00, u01)
    float2 f1 = __half22float2(hb);   // (u10, u11)

    float area = ox0 * oy0 * f0.x;
    area += ox0 * oy1 * f0.y;
    area += ox1 * oy0 * f1.x;
    area += ox1 * oy1 * f1.y;
    return area;
}

__global__ __launch_bounds__(256, 4)
void route_area_kernel(const float* __restrict__ pos,
                       const float* __restrict__ sx,
                       const float* __restrict__ sy,
                       const int*   __restrict__ idx,
                       float*       __restrict__ out,
                       int n, int nidx)
{
    const int t = blockIdx.x * blockDim.x + threadIdx.x;
    const int S = gridDim.x * blockDim.x;

    int   j[ITEMS];
    float x[ITEMS], y[ITEMS], w[ITEMS], h[ITEMS];
    uint2 uu[ITEMS];

    // Phase A: idx loads AND speculative x,y,w,h loads (assuming idx[k]==k),
    // all independent, all issued back-to-back at T0.
    #pragma unroll
    for (int i = 0; i < ITEMS; i++) {
        int k = t + i * S;
        bool act = (k < nidx);
        int ks = act ? k : 0;
        j[i] = act ? __ldg(&idx[k]) : -1;
        x[i] = __ldcs(&pos[ks]);
        y[i] = __ldcs(&pos[ks + n]);
        w[i] = __ldcs(&sx[ks]);
        h[i] = __ldcs(&sy[ks]);
    }

    // Warp-uniform speculation check: one branch per warp, not per item.
    bool ok = true;
    #pragma unroll
    for (int i = 0; i < ITEMS; i++) {
        int k = t + i * S;
        ok &= (j[i] < 0) || (j[i] == k);
    }

    if (__all_sync(0xffffffffu, ok)) {
        // ---- HOT dense path: speculation valid, j[] dead from here ----
        // Gathers issue as soon as x,y arrive (~620 cyc, not ~1250).
        #pragma unroll
        for (int i = 0; i < ITEMS; i++) {
            int bx0 = min(max((int)floorf(x[i]), 0), NBX - 1);
            int by0 = min(max((int)floorf(y[i]), 0), NBY - 1);
            uu[i] = __ldg(&g_packu[bx0 * NBY + by0]);
        }
        #pragma unroll
        for (int i = 0; i < ITEMS; i++) {
            int k = t + i * S;
            float area = area_of(x[i], y[i], w[i], h[i], uu[i]);
            if (k < nidx) out[k] = area;     // coalesced store
        }
    } else {
        // ---- COLD general path: reload everything through j ----
        #pragma unroll
        for (int i = 0; i < ITEMS; i++) {
            int jj = (j[i] >= 0) ? j[i] : 0;
            x[i] = __ldcs(&pos[jj]);
            y[i] = __ldcs(&pos[jj + n]);
        }
        #pragma unroll
        for (int i = 0; i < ITEMS; i++) {
            int bx0 = min(max((int)floorf(x[i]), 0), NBX - 1);
            int by0 = min(max((int)floorf(y[i]), 0), NBY - 1);
            uu[i] = __ldg(&g_packu[bx0 * NBY + by0]);
        }
        #pragma unroll
        for (int i = 0; i < ITEMS; i++) {
            int jj = (j[i] >= 0) ? j[i] : 0;
            w[i] = __ldcs(&sx[jj]);
            h[i] = __ldcs(&sy[jj]);
        }
        #pragma unroll
        for (int i = 0; i < ITEMS; i++) {
            float area = area_of(x[i], y[i], w[i], h[i], uu[i]);
            if (j[i] >= 0) out[j[i]] = area;
        }
    }
}

extern "C" void kernel_launch(void* const* d_in, const int* in_sizes, int n_in,
                              void* d_out, int out_size)
{
    const float* pos  = (const float*)d_in[0];
    const float* sx   = (const float*)d_in[1];
    const float* sy   = (const float*)d_in[2];
    const float* umap = (const float*)d_in[3];
    const int*   idx  = (const int*)d_in[4];
    float* out = (float*)d_out;

    const int n    = in_sizes[1];   // N nodes (pos has 2N)
    const int nidx = in_sizes[4];

    // Zero-fill only needed when the scatter cannot cover all of out.
    if (nidx < out_size) {
        int nout4 = out_size / 4;
        zero_kernel<<<(max(nout4, out_size - nout4 * 4) + 255) / 256, 256>>>(
            (float4*)out, nout4, out, out_size);
    }

    pack_kernel<<<(NBX * NBY + 255) / 256, 256>>>(umap);

    const int threads = 256;
    const int per_grid = threads * ITEMS;
    int blocks = (nidx + per_grid - 1) / per_grid;
    route_area_kernel<<<blocks, threads>>>(pos, sx, sy, idx, out, n, nidx);
}

// round 14
// speedup vs baseline: 1.2718x; 1.2718x over previous
#include <cuda_runtime.h>
#include <cuda_fp16.h>
#include <cstdint>

#define NBX 512
#define NBY 512
#define ITEMS 4

// fp16-packed 2x2 neighborhood of utilization_map (2 MB):
// entry[bx*NBY+by] = { h2(u00,u01), h2(u10,u11) }
__device__ __align__(8) uint2 g_packu[NBX * NBY];

// Table pack only (512*512 entries).
__global__ __launch_bounds__(256)
void pack_kernel(const float* __restrict__ umap)
{
    int t = blockIdx.x * blockDim.x + threadIdx.x;
    if (t >= NBX * NBY) return;
    int bx = t / NBY;
    int by = t % NBY;
    int by1 = min(by + 1, NBY - 1);
    int bx1 = min(bx + 1, NBX - 1);
    float u00 = __ldg(&umap[bx  * NBY + by ]);
    float u01 = __ldg(&umap[bx  * NBY + by1]);
    float u10 = __ldg(&umap[bx1 * NBY + by ]);
    float u11 = __ldg(&umap[bx1 * NBY + by1]);
    __half2 a = __floats2half2_rn(u00, u01);
    __half2 b = __floats2half2_rn(u10, u11);
    uint2 pk;
    pk.x = *reinterpret_cast<unsigned int*>(&a);
    pk.y = *reinterpret_cast<unsigned int*>(&b);
    g_packu[t] = pk;
}

// Zero-fill for the general (non-covering) scatter case.
__global__ __launch_bounds__(256)
void zero_kernel(float4* __restrict__ out4, int nout4,
                 float* __restrict__ out, int nout)
{
    int t = blockIdx.x * blockDim.x + threadIdx.x;
    if (t < nout4) {
        float4 z; z.x = 0.f; z.y = 0.f; z.z = 0.f; z.w = 0.f;
        out4[t] = z;
    }
    int tail = nout4 * 4 + t;
    if (tail < nout) out[tail] = 0.0f;
}

__global__ __launch_bounds__(256, 6)   // ~40 regs -> 6 CTAs/SM = 48 warps (TLP)
void route_area_kernel(const float* __restrict__ pos,
                       const float* __restrict__ sx,
                       const float* __restrict__ sy,
                       const int*   __restrict__ idx,
                       float*       __restrict__ out,
                       int n, int nidx)
{
    const int t = blockIdx.x * blockDim.x + threadIdx.x;
    const int S = gridDim.x * blockDim.x;

    int   j[ITEMS];
    float x[ITEMS], y[ITEMS];
    float w[ITEMS], h[ITEMS];
    uint2 uu[ITEMS];
    int   bx0[ITEMS], by0[ITEMS];

    // Phase A: index loads (coalesced). j = -1 marks inactive.
    #pragma unroll
    for (int i = 0; i < ITEMS; i++) {
        int k = t + i * S;
        j[i] = (k < nidx) ? __ldg(&idx[k]) : -1;
    }

    // Phase B: x, y loads only — the gather address depends only on these.
    #pragma unroll
    for (int i = 0; i < ITEMS; i++) {
        int jj = (j[i] >= 0) ? j[i] : 0;
        x[i] = __ldcs(&pos[jj]);
        y[i] = __ldcs(&pos[jj + n]);
    }

    // Phase C: shortest chain to the gathers; all issue back-to-back.
    #pragma unroll
    for (int i = 0; i < ITEMS; i++) {
        bx0[i] = min(max((int)floorf(x[i]), 0), NBX - 1);
        by0[i] = min(max((int)floorf(y[i]), 0), NBY - 1);
        uu[i] = __ldg(&g_packu[bx0[i] * NBY + by0[i]]);
    }

    // Phase D: w, h loads — latency runs concurrently with the gathers.
    #pragma unroll
    for (int i = 0; i < ITEMS; i++) {
        int jj = (j[i] >= 0) ? j[i] : 0;
        w[i] = __ldcs(&sx[jj]);
        h[i] = __ldcs(&sy[jj]);
    }

    // Phase E: overlap math + unpack + scatter store.
    #pragma unroll
    for (int i = 0; i < ITEMS; i++) {
        float xh = x[i] + w[i];
        float yh = y[i] + h[i];
        float fbx0 = (float)bx0[i];
        float fby0 = (float)by0[i];

        float ox0 = fmaxf(fminf(xh, fbx0 + 1.0f) - fmaxf(x[i], fbx0), 0.0f);
        float ox1 = fmaxf(fminf(xh, fbx0 + 2.0f) - fmaxf(x[i], fbx0 + 1.0f), 0.0f);
        if (bx0[i] + 1 >= NBX) ox1 = 0.0f;

        float oy0 = fmaxf(fminf(yh, fby0 + 1.0f) - fmaxf(y[i], fby0), 0.0f);
        float oy1 = fmaxf(fminf(yh, fby0 + 2.0f) - fmaxf(y[i], fby0 + 1.0f), 0.0f);
        if (by0[i] + 1 >= NBY) oy1 = 0.0f;

        __half2 ha = *reinterpret_cast<__half2*>(&uu[i].x);
        __half2 hb = *reinterpret_cast<__half2*>(&uu[i].y);
        float2 f0 = __half22float2(ha);   // (u00, u01)
        float2 f1 = __half22float2(hb);   // (u10, u11)

        float area = ox0 * oy0 * f0.x;
        area += ox0 * oy1 * f0.y;
        area += ox1 * oy0 * f1.x;
        area += ox1 * oy1 * f1.y;

        if (j[i] >= 0) out[j[i]] = area;
    }
}

extern "C" void kernel_launch(void* const* d_in, const int* in_sizes, int n_in,
                              void* d_out, int out_size)
{
    const float* pos  = (const float*)d_in[0];
    const float* sx   = (const float*)d_in[1];
    const float* sy   = (const float*)d_in[2];
    const float* umap = (const float*)d_in[3];
    const int*   idx  = (const int*)d_in[4];
    float* out = (float*)d_out;

    const int n    = in_sizes[1];   // N nodes (pos has 2N)
    const int nidx = in_sizes[4];

    // Zero-fill only needed when the scatter cannot cover all of out.
    if (nidx < out_size) {
        int nout4 = out_size / 4;
        zero_kernel<<<(max(nout4, out_size - nout4 * 4) + 255) / 256, 256>>>(
            (float4*)out, nout4, out, out_size);
    }

    pack_kernel<<<(NBX * NBY + 255) / 256, 256>>>(umap);

    const int threads = 256;
    const int per_grid = threads * ITEMS;
    int blocks = (nidx + per_grid - 1) / per_grid;
    route_area_kernel<<<blocks, threads>>>(pos, sx, sy, idx, out, n, nidx);
}